// round 1
// baseline (speedup 1.0000x reference)
#include <cuda_runtime.h>
#include <cstdint>
#include <cfloat>

#define NQ 32
#define DIM 128
#define KTOP 10
#define TPB 256
#define NBLK 592
#define WPB (TPB / 32)
#define NWARPS (NBLK * WPB)   // 4736

// ---- static device scratch (no allocations allowed) ----
__device__ float g_qn[DIM * NQ];                    // normalized queries, [d][q] layout
__device__ float g_candS[NWARPS * NQ * KTOP];       // per-warp candidate scores
__device__ int   g_candI[NWARPS * NQ * KTOP];       // per-warp candidate indices

// ---- packed f32x2 helpers (sm_103a) ----
__device__ __forceinline__ unsigned long long ffma2(unsigned long long a,
                                                    unsigned long long b,
                                                    unsigned long long c) {
    unsigned long long r;
    asm("fma.rn.f32x2 %0, %1, %2, %3;" : "=l"(r) : "l"(a), "l"(b), "l"(c));
    return r;
}
__device__ __forceinline__ unsigned long long dup2(float v) {
    unsigned long long r;
    unsigned u = __float_as_uint(v);
    asm("mov.b64 %0, {%1, %1};" : "=l"(r) : "r"(u));
    return r;
}

// ============================================================
// Kernel 1: normalize queries -> g_qn[d][q]
// 32 warps, warp q handles query q; lane covers 4 dims.
// ============================================================
__global__ void normalize_queries(const float* __restrict__ q) {
    int qi = threadIdx.x >> 5;
    int lane = threadIdx.x & 31;
    float4 v = ((const float4*)q)[qi * (DIM / 4) + lane];
    float ss = v.x * v.x + v.y * v.y + v.z * v.z + v.w * v.w;
    #pragma unroll
    for (int o = 16; o; o >>= 1) ss += __shfl_xor_sync(0xffffffffu, ss, o);
    float inv = 1.0f / fmaxf(sqrtf(ss), 1e-12f);
    int d = lane * 4;
    g_qn[(d + 0) * NQ + qi] = v.x * inv;
    g_qn[(d + 1) * NQ + qi] = v.y * inv;
    g_qn[(d + 2) * NQ + qi] = v.z * inv;
    g_qn[(d + 3) * NQ + qi] = v.w * inv;
}

// ============================================================
// Kernel 2: fused scores + per-warp top-10
// ============================================================
__device__ __forceinline__ void topk_try(
    int warp, int lane, int q, float sv, int r,
    float (*topS)[NQ][KTOP], int (*topI)[NQ][KTOP], float (*kminS)[NQ])
{
    float kmin = kminS[warp][q];
    unsigned m = __ballot_sync(0xffffffffu, sv > kmin);
    if (m) {
        unsigned mm = m;
        while (mm) {
            int j = __ffs(mm) - 1;
            mm &= mm - 1;
            float sj = __shfl_sync(0xffffffffu, sv, j);
            int   ij = __shfl_sync(0xffffffffu, r, j);
            if (lane == 0) {
                float mn = topS[warp][q][0]; int mp = 0;
                #pragma unroll
                for (int t = 1; t < KTOP; t++) {
                    float v = topS[warp][q][t];
                    if (v < mn) { mn = v; mp = t; }
                }
                if (sj > mn) {
                    topS[warp][q][mp] = sj;
                    topI[warp][q][mp] = ij;
                    mn = topS[warp][q][0];
                    #pragma unroll
                    for (int t = 1; t < KTOP; t++) mn = fminf(mn, topS[warp][q][t]);
                    kminS[warp][q] = mn;
                }
            }
        }
        __syncwarp();
    }
}

__global__ void __launch_bounds__(TPB) score_topk(const float* __restrict__ corpus, int nrows) {
    __shared__ __align__(16) float qsm[DIM * NQ];      // 16 KB
    __shared__ float topS[WPB][NQ][KTOP];              // 10 KB
    __shared__ int   topI[WPB][NQ][KTOP];              // 10 KB
    __shared__ float kminS[WPB][NQ];                   // 1 KB

    for (int i = threadIdx.x; i < DIM * NQ; i += TPB) qsm[i] = g_qn[i];
    for (int i = threadIdx.x; i < WPB * NQ * KTOP; i += TPB) {
        ((float*)topS)[i] = -FLT_MAX;
        ((int*)topI)[i] = 0;
    }
    for (int i = threadIdx.x; i < WPB * NQ; i += TPB) ((float*)kminS)[i] = -FLT_MAX;
    __syncthreads();

    const int warp = threadIdx.x >> 5;
    const int lane = threadIdx.x & 31;
    const int stride = gridDim.x * blockDim.x;
    const int rb0 = blockIdx.x * blockDim.x + warp * 32;

    for (int rb = rb0; rb < nrows; rb += stride) {
        const int r = rb + lane;
        const bool valid = (r < nrows);

        unsigned long long acc[16];
        #pragma unroll
        for (int p = 0; p < 16; p++) acc[p] = 0ull;
        float n2 = 0.0f;

        if (valid) {
            const float4* rp = (const float4*)(corpus + (size_t)r * DIM);
            #pragma unroll 4
            for (int d4 = 0; d4 < DIM / 4; ++d4) {
                float4 c = rp[d4];
                n2 = fmaf(c.x, c.x, n2);
                n2 = fmaf(c.y, c.y, n2);
                n2 = fmaf(c.z, c.z, n2);
                n2 = fmaf(c.w, c.w, n2);
                const ulonglong2* q0 = (const ulonglong2*)(qsm + (d4 * 4 + 0) * NQ);
                const ulonglong2* q1 = (const ulonglong2*)(qsm + (d4 * 4 + 1) * NQ);
                const ulonglong2* q2 = (const ulonglong2*)(qsm + (d4 * 4 + 2) * NQ);
                const ulonglong2* q3 = (const ulonglong2*)(qsm + (d4 * 4 + 3) * NQ);
                unsigned long long vx = dup2(c.x);
                unsigned long long vy = dup2(c.y);
                unsigned long long vz = dup2(c.z);
                unsigned long long vw = dup2(c.w);
                #pragma unroll
                for (int p2 = 0; p2 < 8; ++p2) {
                    ulonglong2 t;
                    t = q0[p2];
                    acc[2 * p2]     = ffma2(vx, t.x, acc[2 * p2]);
                    acc[2 * p2 + 1] = ffma2(vx, t.y, acc[2 * p2 + 1]);
                    t = q1[p2];
                    acc[2 * p2]     = ffma2(vy, t.x, acc[2 * p2]);
                    acc[2 * p2 + 1] = ffma2(vy, t.y, acc[2 * p2 + 1]);
                    t = q2[p2];
                    acc[2 * p2]     = ffma2(vz, t.x, acc[2 * p2]);
                    acc[2 * p2 + 1] = ffma2(vz, t.y, acc[2 * p2 + 1]);
                    t = q3[p2];
                    acc[2 * p2]     = ffma2(vw, t.x, acc[2 * p2]);
                    acc[2 * p2 + 1] = ffma2(vw, t.y, acc[2 * p2 + 1]);
                }
            }
        }

        float inv = 1.0f / fmaxf(sqrtf(n2), 1e-12f);

        #pragma unroll
        for (int p = 0; p < 16; ++p) {
            unsigned lo, hi;
            asm("mov.b64 {%0, %1}, %2;" : "=r"(lo), "=r"(hi) : "l"(acc[p]));
            float s0 = valid ? __uint_as_float(lo) * inv : -FLT_MAX;
            float s1 = valid ? __uint_as_float(hi) * inv : -FLT_MAX;
            topk_try(warp, lane, 2 * p,     s0, r, topS, topI, kminS);
            topk_try(warp, lane, 2 * p + 1, s1, r, topS, topI, kminS);
        }
    }

    __syncthreads();
    const int wg = blockIdx.x * WPB + warp;
    if (lane < KTOP) {
        for (int q = 0; q < NQ; q++) {
            g_candS[(wg * NQ + q) * KTOP + lane] = topS[warp][q][lane];
            g_candI[(wg * NQ + q) * KTOP + lane] = topI[warp][q][lane];
        }
    }
}

// ============================================================
// Kernel 3: per-query merge of all warp candidate lists
// jax top_k semantics: sorted desc, ties -> lower index first
// ============================================================
__global__ void merge_topk(float* __restrict__ out) {
    const int q = blockIdx.x;

    float ls[KTOP];
    int   li[KTOP];
    #pragma unroll
    for (int t = 0; t < KTOP; t++) { ls[t] = -FLT_MAX; li[t] = 0x7fffffff; }

    for (int j = threadIdx.x; j < NWARPS * KTOP; j += blockDim.x) {
        int w = j / KTOP;
        int t = j - w * KTOP;
        float s = g_candS[(w * NQ + q) * KTOP + t];
        int   i = g_candI[(w * NQ + q) * KTOP + t];
        float mn = ls[0]; int mp = 0;
        #pragma unroll
        for (int u = 1; u < KTOP; u++)
            if (ls[u] < mn) { mn = ls[u]; mp = u; }
        if (s > mn) { ls[mp] = s; li[mp] = i; }
    }

    __shared__ float sS[256 * KTOP];
    __shared__ int   sI[256 * KTOP];
    __shared__ float wS[8];
    __shared__ int   wI[8];
    __shared__ int   wP[8];

    #pragma unroll
    for (int t = 0; t < KTOP; t++) {
        sS[threadIdx.x * KTOP + t] = ls[t];
        sI[threadIdx.x * KTOP + t] = li[t];
    }
    __syncthreads();

    const int warp = threadIdx.x >> 5;
    const int lane = threadIdx.x & 31;

    for (int round = 0; round < KTOP; ++round) {
        float bs = -FLT_MAX; int bi = 0x7fffffff; int bp = -1;
        #pragma unroll
        for (int t = 0; t < KTOP; t++) {
            float s = sS[threadIdx.x * KTOP + t];
            int   i = sI[threadIdx.x * KTOP + t];
            if (s > bs || (s == bs && i < bi)) { bs = s; bi = i; bp = threadIdx.x * KTOP + t; }
        }
        #pragma unroll
        for (int o = 16; o; o >>= 1) {
            float os = __shfl_down_sync(0xffffffffu, bs, o);
            int   oi = __shfl_down_sync(0xffffffffu, bi, o);
            int   op = __shfl_down_sync(0xffffffffu, bp, o);
            if (os > bs || (os == bs && oi < bi)) { bs = os; bi = oi; bp = op; }
        }
        if (lane == 0) { wS[warp] = bs; wI[warp] = bi; wP[warp] = bp; }
        __syncthreads();
        if (threadIdx.x == 0) {
            float cs = wS[0]; int ci = wI[0]; int cp = wP[0];
            #pragma unroll
            for (int w2 = 1; w2 < 8; w2++) {
                if (wS[w2] > cs || (wS[w2] == cs && wI[w2] < ci)) {
                    cs = wS[w2]; ci = wI[w2]; cp = wP[w2];
                }
            }
            out[q * KTOP + round] = cs;                       // top_scores
            out[NQ * KTOP + q * KTOP + round] = (float)ci;    // top_idx (as float)
            sS[cp] = -FLT_MAX;
            sI[cp] = 0x7fffffff;
        }
        __syncthreads();
    }
}

// ============================================================
extern "C" void kernel_launch(void* const* d_in, const int* in_sizes, int n_in,
                              void* d_out, int out_size) {
    const float* queries = (const float*)d_in[0];
    const float* corpus  = (const float*)d_in[1];
    // d_in[2] is k (fixed at 10 == KTOP)
    int nrows = in_sizes[1] / DIM;

    normalize_queries<<<1, NQ * 32>>>(queries);
    score_topk<<<NBLK, TPB>>>(corpus, nrows);
    merge_topk<<<NQ, 256>>>((float*)d_out);
}